// round 17
// baseline (speedup 1.0000x reference)
#include <cuda_runtime.h>
#include <cstdint>

// Problem constants (B=64, C=512, H=W=28, G=8)
#define HWN    784
#define HW4    196
#define CPG    64
#define CPC    16        // channels per CTA (cluster of 4)
#define EPS    1e-5f
#define NTHR   256
#define NTILE  512
#define CSZ    4

#define SLICE_FLOATS (CPC * HWN)          // 12544
#define SLICE_BYTES  (SLICE_FLOATS * 4)   // 50176
#define HALFB        (SLICE_BYTES / 2)    // 25088
#define TILE_FLOATS  (CPG * HWN)          // 50176

// smem layout (floats)
#define OFF_BUF0  0                       // tile-0 slice (12544)
#define OFF_BUF1  SLICE_FLOATS            // tile-1 slice (12544)
#define OFF_SP    (2 * SLICE_FLOATS)      // 25088: own partial s, per tile (2x784)
#define OFF_GATE  (OFF_SP + 2 * HWN)      // 26656 (16B aligned)
#define OFF_MEANS (OFF_GATE + HWN)        // 27440 (16)
#define OFF_RED   (OFF_MEANS + CPC)       // 27456 (18 used)
#define OFF_MBAR  (OFF_RED + 20)          // 27476 even -> 8B aligned; 4 x u64
#define SMEM_FLOATS (OFF_MBAR + 8)
#define SMEM_BYTES  (SMEM_FLOATS * 4)     // 109936 B -> 2 CTAs/SM

__device__ __forceinline__ uint32_t smem_u32(const void* p) {
    uint32_t a;
    asm("{ .reg .u64 t; cvta.to.shared.u64 t, %1; cvt.u32.u64 %0, t; }"
        : "=r"(a) : "l"(p));
    return a;
}

__device__ __forceinline__ uint32_t mapa_u32(uint32_t laddr, int peer) {
    uint32_t r;
    asm("mapa.shared::cluster.u32 %0, %1, %2;" : "=r"(r) : "r"(laddr), "r"(peer));
    return r;
}

// wait (cta-scope acquire) for TMA load barriers
__device__ __forceinline__ void mbar_wait_cta(uint32_t mbar) {
    asm volatile(
        "{\n\t"
        ".reg .pred P;\n\t"
        "WL_%=: mbarrier.try_wait.parity.acquire.cta.shared::cta.b64 P, [%0], 0, 0x989680;\n\t"
        "@P bra WD_%=;\n\t"
        "bra WL_%=;\n\t"
        "WD_%=:\n\t"
        "}" :: "r"(mbar) : "memory");
}

// wait (cluster-scope acquire) for cross-CTA s-partial barriers
__device__ __forceinline__ void mbar_wait_cl(uint32_t mbar) {
    asm volatile(
        "{\n\t"
        ".reg .pred P;\n\t"
        "WL_%=: mbarrier.try_wait.parity.acquire.cluster.shared::cta.b64 P, [%0], 0, 0x989680;\n\t"
        "@P bra WD_%=;\n\t"
        "bra WL_%=;\n\t"
        "WD_%=:\n\t"
        "}" :: "r"(mbar) : "memory");
}

__global__ __launch_bounds__(NTHR, 2) __cluster_dims__(CSZ, 1, 1)
void simam_la_kernel(const float* __restrict__ x,
                     const float* __restrict__ weight,
                     const float* __restrict__ bias,
                     float* __restrict__ out)
{
    extern __shared__ float smem[];
    float*  s_gate  = smem + OFF_GATE;
    float4* s_gate4 = (float4*)s_gate;
    float*  s_means = smem + OFF_MEANS;
    float*  s_red   = smem + OFF_RED;
    const uint32_t mbL0 = smem_u32(smem + OFF_MBAR);       // load barriers
    const uint32_t mbS0 = mbL0 + 16;                       // s-exchange barriers

    const int rank = (int)(blockIdx.x & (CSZ - 1));
    const int cl   = (int)(blockIdx.x >> 2);               // cluster id, 2 tiles each
    const size_t ch_off = (size_t)rank * SLICE_FLOATS;

    const int tid  = threadIdx.x;
    const int w    = tid >> 5;
    const int lane = tid & 31;

    // ---- init mbars ----
    if (tid == 0) {
        asm volatile("mbarrier.init.shared::cta.b64 [%0], 1;"   :: "r"(mbL0)      : "memory");
        asm volatile("mbarrier.init.shared::cta.b64 [%0], 1;"   :: "r"(mbL0 + 8)  : "memory");
        asm volatile("mbarrier.init.shared::cta.b64 [%0], 784;" :: "r"(mbS0)      : "memory");
        asm volatile("mbarrier.init.shared::cta.b64 [%0], 784;" :: "r"(mbS0 + 8)  : "memory");
    }
    __syncthreads();

    // ---- issue ALL loads for both tiles up front ----
    if (tid == 0) {
        const uint32_t sx0 = smem_u32(smem);
        #pragma unroll
        for (int t = 0; t < 2; t++) {
            const int tile = cl * 2 + t;
            const char* src = (const char*)(x + (size_t)tile * TILE_FLOATS + ch_off);
            const uint32_t mb  = mbL0 + t * 8;
            const uint32_t dst = sx0 + t * SLICE_BYTES;
            asm volatile("mbarrier.arrive.expect_tx.shared::cta.b64 _, [%0], %1;"
                         :: "r"(mb), "r"((uint32_t)SLICE_BYTES) : "memory");
            asm volatile(
                "cp.async.bulk.shared::cluster.global.mbarrier::complete_tx::bytes "
                "[%0], [%1], %2, [%3];"
                :: "r"(dst), "l"(src), "r"((uint32_t)HALFB), "r"(mb) : "memory");
            asm volatile(
                "cp.async.bulk.shared::cluster.global.mbarrier::complete_tx::bytes "
                "[%0], [%1], %2, [%3];"
                :: "r"(dst + HALFB), "l"(src + HALFB), "r"((uint32_t)HALFB), "r"(mb) : "memory");
        }
    }
    // one aligned cluster sync: peers' mbS init visible before any remote arrive
    asm volatile("barrier.cluster.arrive.aligned;" ::: "memory");
    asm volatile("barrier.cluster.wait.aligned;"   ::: "memory");

    #pragma unroll
    for (int t = 0; t < 2; t++) {
        const int tile = cl * 2 + t;
        const int g    = tile & 7;
        float* buf = smem + t * SLICE_FLOATS;
        float4* sp4 = (float4*)(smem + OFF_SP + t * HWN);   // own partial s slot

        mbar_wait_cta(mbL0 + t * 8);

        // ---- per-channel means: 8 warps x 2 channels ----
        #pragma unroll
        for (int i = 0; i < 2; i++) {
            const int c = w * 2 + i;
            const float4* row = (const float4*)(buf + c * HWN);
            float cs = 0.f;
            #pragma unroll
            for (int k = 0; k < 7; k++) {
                const int j = lane + 32 * k;
                if (j < HW4) {
                    float4 v = row[j];
                    cs += (v.x + v.y) + (v.z + v.w);
                }
            }
            #pragma unroll
            for (int o = 16; o; o >>= 1) cs += __shfl_xor_sync(0xffffffffu, cs, o);
            if (lane == 0) s_means[c] = cs * (1.0f / HWN);
        }
        __syncthreads();

        // ---- partial s over own 16 channels; publish + remote arrive ----
        float4 acc = make_float4(0.f, 0.f, 0.f, 0.f);
        if (tid < HW4) {
            const float4* col = (const float4*)buf + tid;
            #pragma unroll
            for (int c = 0; c < CPC; c++) {
                const float  m = s_means[c];
                const float4 v = col[c * HW4];
                acc.x += m * v.x;
                acc.y += m * v.y;
                acc.z += m * v.z;
                acc.w += m * v.w;
            }
            sp4[tid] = acc;                       // own partial, local STS
            const uint32_t mb = mbS0 + t * 8;
            #pragma unroll
            for (int d = 0; d < CSZ; d++) {       // release covers this thread's STS
                const uint32_t rb = mapa_u32(mb, d);
                asm volatile("mbarrier.arrive.release.cluster.shared::cluster.b64 _, [%0];"
                             :: "r"(rb) : "memory");
            }
        }
        mbar_wait_cl(mbS0 + t * 8);

        // ---- pull all 4 partials (fixed order -> deterministic), total s ----
        float4 tot = make_float4(0.f, 0.f, 0.f, 0.f);
        if (tid < HW4) {
            const uint32_t laddr = smem_u32(&sp4[tid]);
            #pragma unroll
            for (int d = 0; d < CSZ; d++) {
                const uint32_t ra = mapa_u32(laddr, d);
                float4 p;
                asm volatile("ld.shared::cluster.v4.f32 {%0,%1,%2,%3}, [%4];"
                             : "=f"(p.x), "=f"(p.y), "=f"(p.z), "=f"(p.w)
                             : "r"(ra));
                tot.x += p.x; tot.y += p.y; tot.z += p.z; tot.w += p.w;
            }
        }

        // ---- stats (redundant per CTA, deterministic) ----
        float ls = 0.f, lq = 0.f;
        if (tid < HW4) {
            ls = (tot.x + tot.y) + (tot.z + tot.w);
            lq = tot.x * tot.x + tot.y * tot.y + tot.z * tot.z + tot.w * tot.w;
        }
        #pragma unroll
        for (int o = 16; o; o >>= 1) {
            ls += __shfl_xor_sync(0xffffffffu, ls, o);
            lq += __shfl_xor_sync(0xffffffffu, lq, o);
        }
        if (lane == 0) { s_red[w] = ls; s_red[8 + w] = lq; }
        __syncthreads();
        if (tid == 0) {
            float ts = 0.f, tq = 0.f;
            #pragma unroll
            for (int i = 0; i < 8; i++) { ts += s_red[i]; tq += s_red[8 + i]; }
            const float mu  = ts * (1.0f / HWN);
            const float var = tq * (1.0f / HWN) - mu * mu;
            s_red[16] = mu;
            s_red[17] = rsqrtf(var + EPS);
        }
        __syncthreads();

        // ---- gate ----
        {
            const float mu = s_red[16];
            const float rs = s_red[17];
            const float wg = weight[g];
            const float bb = bias[g];
            if (tid < HW4) {
                float4 gt;
                gt.x = 1.0f / (1.0f + __expf(-((tot.x - mu) * rs * wg + bb)));
                gt.y = 1.0f / (1.0f + __expf(-((tot.y - mu) * rs * wg + bb)));
                gt.z = 1.0f / (1.0f + __expf(-((tot.z - mu) * rs * wg + bb)));
                gt.w = 1.0f / (1.0f + __expf(-((tot.w - mu) * rs * wg + bb)));
                s_gate4[tid] = gt;
            }
        }
        __syncthreads();

        // ---- in-place multiply ----
        #pragma unroll
        for (int i = 0; i < 2; i++) {
            const int c = w * 2 + i;
            float4* row = (float4*)(buf + c * HWN);
            #pragma unroll
            for (int k = 0; k < 7; k++) {
                const int j = lane + 32 * k;
                if (j < HW4) {
                    float4 v = row[j];
                    const float4 gt = s_gate4[j];
                    v.x *= gt.x; v.y *= gt.y; v.z *= gt.z; v.w *= gt.w;
                    row[j] = v;
                }
            }
        }
        __syncthreads();

        // ---- TMA bulk store this tile's slice ----
        if (tid == 0) {
            char* dstg = (char*)(out + (size_t)tile * TILE_FLOATS + ch_off);
            const uint32_t src = smem_u32(smem) + t * SLICE_BYTES;
            asm volatile("fence.proxy.async.shared::cta;" ::: "memory");
            asm volatile("cp.async.bulk.global.shared::cta.bulk_group [%0], [%1], %2;"
                         :: "l"(dstg), "r"(src), "r"((uint32_t)HALFB) : "memory");
            asm volatile("cp.async.bulk.global.shared::cta.bulk_group [%0], [%1], %2;"
                         :: "l"(dstg + HALFB), "r"(src + HALFB), "r"((uint32_t)HALFB) : "memory");
            asm volatile("cp.async.bulk.commit_group;" ::: "memory");
        }
    }

    // drain stores, then cluster sync so no CTA exits while peers may still
    // read its s-partials via DSMEM
    if (tid == 0) {
        asm volatile("cp.async.bulk.wait_group 0;" ::: "memory");
    }
    __syncthreads();
    asm volatile("barrier.cluster.arrive.aligned;" ::: "memory");
    asm volatile("barrier.cluster.wait.aligned;"   ::: "memory");
}

extern "C" void kernel_launch(void* const* d_in, const int* in_sizes, int n_in,
                              void* d_out, int out_size)
{
    const float* x  = (const float*)d_in[0];
    const float* wt = (const float*)d_in[1];
    const float* bs = (const float*)d_in[2];
    float* out = (float*)d_out;

    cudaFuncSetAttribute(simam_la_kernel,
                         cudaFuncAttributeMaxDynamicSharedMemorySize, SMEM_BYTES);
    simam_la_kernel<<<(NTILE / 2) * CSZ, NTHR, SMEM_BYTES>>>(x, wt, bs, out);
}